// round 1
// baseline (speedup 1.0000x reference)
#include <cuda_runtime.h>
#include <cstdint>

#define BB 32
#define CC 128
#define LL 1024
#define OO 128
#define PP 1017
#define FF 8
#define KC 32      // k per chunk = 4 c * 8 f
#define CPC 4
#define WA 132     // As row pitch (floats), mult of 4 for LDS.128 alignment
#define WB 36      // Bs row pitch

__device__ __forceinline__ unsigned long long pack2(float lo, float hi) {
    unsigned long long r;
    asm("mov.b64 %0, {%1, %2};" : "=l"(r) : "f"(lo), "f"(hi));
    return r;
}
__device__ __forceinline__ void fma2(unsigned long long& d, unsigned long long a, unsigned long long b) {
    asm("fma.rn.f32x2 %0, %1, %2, %0;" : "+l"(d) : "l"(a), "l"(b));
}
__device__ __forceinline__ void unpack2(unsigned long long v, float& lo, float& hi) {
    asm("mov.b64 {%0, %1}, %2;" : "=f"(lo), "=f"(hi) : "l"(v));
}

__global__ __launch_bounds__(64, 8) void loc1d_kernel(
    const float* __restrict__ x, const float* __restrict__ filt, float* __restrict__ out)
{
    __shared__ __align__(16) float As[KC][WA];   // [k][o], k-major for vector a-loads
    __shared__ __align__(16) float Bs[KC][WB];   // [k][b]

    const int p   = blockIdx.x;
    const int tid = threadIdx.x;
    const int otid = tid >> 2;     // 0..15
    const int btid = tid & 3;      // 0..3
    const int o0 = otid * 8;
    const int b0 = btid * 8;

    unsigned long long acc[8][4];  // [o-idx][b-pair], 64 fp32 accumulators
#pragma unroll
    for (int i = 0; i < 8; i++)
#pragma unroll
        for (int j = 0; j < 4; j++) acc[i][j] = 0ull;

    const long long OSTR = (long long)CC * PP * FF;  // filt o-stride (floats)
    const int CSTR = PP * FF;                        // filt c-stride

    const int xb  = tid & 31;      // x-loader batch
    const int xch = tid >> 5;      // x-loader c-group (0/1)

    for (int c0 = 0; c0 < CC; c0 += CPC) {
        // --- load filt chunk: 128 o x 4 c x 8 f -> As[k][o], k = cp*8+f ---
        // v = [cp:2][o:7][fh:1] : warp covers 16 consecutive o x 2 fh -> full
        // 32B sectors in GMEM, conflict-free STS banks (16fh+4j+o spans all 32).
#pragma unroll
        for (int i = 0; i < 16; i++) {
            int v  = tid + 64 * i;
            int fh = v & 1;
            int o  = (v >> 1) & 127;
            int cp = v >> 8;
            const float4 f4 = *reinterpret_cast<const float4*>(
                filt + (long long)o * OSTR + (long long)(c0 + cp) * CSTR + p * FF + fh * 4);
            int k = cp * 8 + fh * 4;
            As[k + 0][o] = f4.x;
            As[k + 1][o] = f4.y;
            As[k + 2][o] = f4.z;
            As[k + 3][o] = f4.w;
        }
        // --- load x chunk: 32 b x 4 c x 8 f -> Bs[k][b] (scalar: p unaligned) ---
#pragma unroll
        for (int cc = 0; cc < 2; cc++) {
            int cp = xch + cc * 2;
            const float* xp = x + ((long long)xb * CC + (c0 + cp)) * LL + p;
#pragma unroll
            for (int j = 0; j < FF; j++) Bs[cp * 8 + j][xb] = xp[j];
        }
        __syncthreads();

        // --- 8x8 register-tile GEMM on the chunk, packed f32x2 FMAs ---
#pragma unroll 8
        for (int k = 0; k < KC; k++) {
            const float4 aL = *reinterpret_cast<const float4*>(&As[k][o0]);
            const float4 aH = *reinterpret_cast<const float4*>(&As[k][o0 + 4]);
            const float4 bL = *reinterpret_cast<const float4*>(&Bs[k][b0]);
            const float4 bH = *reinterpret_cast<const float4*>(&Bs[k][b0 + 4]);
            unsigned long long bp[4];
            bp[0] = pack2(bL.x, bL.y);
            bp[1] = pack2(bL.z, bL.w);
            bp[2] = pack2(bH.x, bH.y);
            bp[3] = pack2(bH.z, bH.w);
            const float av[8] = {aL.x, aL.y, aL.z, aL.w, aH.x, aH.y, aH.z, aH.w};
#pragma unroll
            for (int i = 0; i < 8; i++) {
                unsigned long long ap = pack2(av[i], av[i]);
#pragma unroll
                for (int j = 0; j < 4; j++) fma2(acc[i][j], ap, bp[j]);
            }
        }
        __syncthreads();
    }

    // --- epilogue: scale by (C*F)^-0.5 = 1/32, scatter to out[b][o][p] ---
    const float scale = 0.03125f;
#pragma unroll
    for (int i = 0; i < 8; i++) {
        const int o = o0 + i;
        float* op = out + (long long)o * PP + p;
#pragma unroll
        for (int j = 0; j < 4; j++) {
            float lo, hi;
            unpack2(acc[i][j], lo, hi);
            const int b = b0 + j * 2;
            op[(long long)b * (OO * PP)]       = lo * scale;
            op[(long long)(b + 1) * (OO * PP)] = hi * scale;
        }
    }
}

extern "C" void kernel_launch(void* const* d_in, const int* in_sizes, int n_in,
                              void* d_out, int out_size) {
    const float* x    = (const float*)d_in[0];
    const float* filt = (const float*)d_in[1];
    float* out        = (float*)d_out;
    loc1d_kernel<<<PP, 64>>>(x, filt, out);
}